// round 4
// baseline (speedup 1.0000x reference)
#include <cuda_runtime.h>

// RoIAlign matching the JAX reference.
//   features: (B=2, C=256, H=200, W=200) fp32
//   rois:     (N=512, 5)  [batch_idx, x1, y1, x2, y2] image coords
//   out:      (N, C, 7, 7) fp32
// 7x7 pool, scale 1/16, sampling_ratio 2, mean of 4 samples.
// R2: alignment-aware float4 corner-pair loads (rows are 16B-aligned since
// W=200 -> 800B row pitch). Cuts gather LDG count per output from 16 to ~10.

#define POOLED 7
#define SPATIAL_SCALE 0.0625f

__global__ __launch_bounds__(256)
void roi_align_kernel(const float* __restrict__ feat,
                      const float* __restrict__ rois,
                      float* __restrict__ out,
                      int N, int C, int H, int W)
{
    int idx = blockIdx.x * blockDim.x + threadIdx.x;
    int total = N * C * POOLED * POOLED;
    if (idx >= total) return;

    // idx = ((n*C + c)*7 + ph)*7 + pw  (pw fastest -> coalesced out, x-local gathers)
    int pw = idx % POOLED;
    int ph = (idx / POOLED) % POOLED;
    int c  = (idx / (POOLED * POOLED)) % C;
    int n  = idx / (POOLED * POOLED * C);

    const float* r = rois + n * 5;
    int   b  = (int)__ldg(r + 0);
    float x1 = __ldg(r + 1) * SPATIAL_SCALE;
    float y1 = __ldg(r + 2) * SPATIAL_SCALE;
    float x2 = __ldg(r + 3) * SPATIAL_SCALE;
    float y2 = __ldg(r + 4) * SPATIAL_SCALE;

    float bin_w = fmaxf(x2 - x1, 1.0f) * (1.0f / POOLED);
    float bin_h = fmaxf(y2 - y1, 1.0f) * (1.0f / POOLED);

    const float* fc = feat + ((size_t)b * C + c) * (size_t)(H * W);

    float acc = 0.0f;

    #pragma unroll
    for (int iy = 0; iy < 2; iy++) {
        float yc = y1 + ((float)ph + 0.25f + 0.5f * (float)iy) * bin_h;
        bool  vy = (yc >= -1.0f) && (yc <= (float)H);
        float cy = fmaxf(yc, 0.0f);
        int   yl = min((int)cy, H - 1);          // cy >= 0, so trunc == floor
        int   yh = min(yl + 1, H - 1);
        float fy = (yl >= H - 1) ? 0.0f : (cy - (float)yl);

        const float* rowl = fc + (size_t)yl * W;  // 16B-aligned (W*4 = 800)
        const float* rowh = fc + (size_t)yh * W;

        #pragma unroll
        for (int ix = 0; ix < 2; ix++) {
            float xc = x1 + ((float)pw + 0.25f + 0.5f * (float)ix) * bin_w;
            bool  vx = (xc >= -1.0f) && (xc <= (float)W);
            float cx = fmaxf(xc, 0.0f);
            int   xl = min((int)cx, W - 1);
            float fx = (xl >= W - 1) ? 0.0f : (cx - (float)xl);

            int a  = xl >> 2;
            int rr = xl & 3;

            float4 ql = __ldg((const float4*)rowl + a);
            float4 qh = __ldg((const float4*)rowh + a);

            float v00 = (rr == 0) ? ql.x : (rr == 1) ? ql.y : (rr == 2) ? ql.z : ql.w;
            float v10 = (rr == 0) ? qh.x : (rr == 1) ? qh.y : (rr == 2) ? qh.z : qh.w;

            float v01, v11;
            if (rr != 3) {
                v01 = (rr == 0) ? ql.y : (rr == 1) ? ql.z : ql.w;
                v11 = (rr == 0) ? qh.y : (rr == 1) ? qh.z : qh.w;
            } else if (fx != 0.0f) {
                // crossing the float4 boundary; xl+1 <= W-1 guaranteed (fx != 0)
                v01 = __ldg(rowl + xl + 1);
                v11 = __ldg(rowh + xl + 1);
            } else {
                v01 = v00;   // fx == 0 -> value unused, keep it finite
                v11 = v10;
            }

            if (vy && vx) {
                float top = v00 + fx * (v01 - v00);
                float bot = v10 + fx * (v11 - v10);
                acc += top + fy * (bot - top);
            }
        }
    }

    out[idx] = acc * 0.25f;
}

extern "C" void kernel_launch(void* const* d_in, const int* in_sizes, int n_in,
                              void* d_out, int out_size)
{
    const float* feat = (const float*)d_in[0];   // (2,256,200,200) fp32
    const float* rois = (const float*)d_in[1];   // (512,5) fp32
    float* out = (float*)d_out;                  // (512,256,7,7) fp32

    const int C = 256, H = 200, W = 200;
    int N = in_sizes[1] / 5;
    (void)n_in; (void)out_size;

    int total = N * C * POOLED * POOLED;
    int threads = 256;
    int blocks = (total + threads - 1) / threads;
    roi_align_kernel<<<blocks, threads>>>(feat, rois, out, N, C, H, W);
}

// round 5
// speedup vs baseline: 1.1531x; 1.1531x over previous
#include <cuda_runtime.h>

// RoIAlign matching the JAX reference.
//   features: (B=2, C=256, H=200, W=200) fp32
//   rois:     (N=512, 5)  [batch_idx, x1, y1, x2, y2] image coords
//   out:      (N, C, 7, 7) fp32
// 7x7 pool, scale 1/16, sampling_ratio 2, mean of 4 samples.
//
// R4: back to R1's scalar-gather pattern (float4 experiment regressed: wide
// divergent loads cost ~4x wavefronts/instr). New: each thread handles 4
// channels of one (n, ph, pw); the 16 (offset, weight) pairs are computed
// ONCE and reused across channels, cutting ALU issue pressure ~4x so the
// L1tex pipe (the binding resource at 82%) can be driven to saturation.

#define POOLED 7
#define SPATIAL_SCALE 0.0625f
#define CPT 4              // channels per thread

__global__ __launch_bounds__(256)
void roi_align_kernel(const float* __restrict__ feat,
                      const float* __restrict__ rois,
                      float* __restrict__ out,
                      int N, int C, int H, int W)
{
    const int cg = C / CPT;                 // channel groups (64)
    int idx = blockIdx.x * blockDim.x + threadIdx.x;
    int total = N * cg * POOLED * POOLED;
    if (idx >= total) return;

    // idx = ((n*cg + c0)*49 + p), p = ph*7+pw fastest -> warp lanes are
    // consecutive bin positions of ONE channel (same gather locality as R1).
    int p  = idx % (POOLED * POOLED);
    int t  = idx / (POOLED * POOLED);
    int c0 = t % cg;
    int n  = t / cg;
    int ph = p / POOLED;
    int pw = p % POOLED;

    const float* r = rois + n * 5;
    int   b  = (int)__ldg(r + 0);
    float x1 = __ldg(r + 1) * SPATIAL_SCALE;
    float y1 = __ldg(r + 2) * SPATIAL_SCALE;
    float x2 = __ldg(r + 3) * SPATIAL_SCALE;
    float y2 = __ldg(r + 4) * SPATIAL_SCALE;

    float bin_w = fmaxf(x2 - x1, 1.0f) * (1.0f / POOLED);
    float bin_h = fmaxf(y2 - y1, 1.0f) * (1.0f / POOLED);

    // ---- compute 16 (offset, weight) pairs once ----
    int   off[16];
    float wgt[16];

    #pragma unroll
    for (int iy = 0; iy < 2; iy++) {
        float yc = y1 + ((float)ph + 0.25f + 0.5f * (float)iy) * bin_h;
        bool  vy = (yc >= -1.0f) && (yc <= (float)H);
        float cy = fmaxf(yc, 0.0f);
        int   yl = min((int)cy, H - 1);        // cy >= 0 -> trunc == floor
        int   yh = min(yl + 1, H - 1);
        float fy = (yl >= H - 1) ? 0.0f : (cy - (float)yl);

        #pragma unroll
        for (int ix = 0; ix < 2; ix++) {
            float xc = x1 + ((float)pw + 0.25f + 0.5f * (float)ix) * bin_w;
            bool  vx = (xc >= -1.0f) && (xc <= (float)W);
            float cx = fmaxf(xc, 0.0f);
            int   xl = min((int)cx, W - 1);
            int   xh = min(xl + 1, W - 1);
            float fx = (xl >= W - 1) ? 0.0f : (cx - (float)xl);

            float w = (vy && vx) ? 0.25f : 0.0f;   // fold mask + mean into weights
            int k = (iy * 2 + ix) * 4;
            int rl = yl * W, rh = yh * W;
            off[k + 0] = rl + xl;  wgt[k + 0] = w * (1.0f - fy) * (1.0f - fx);
            off[k + 1] = rl + xh;  wgt[k + 1] = w * (1.0f - fy) * fx;
            off[k + 2] = rh + xl;  wgt[k + 2] = w * fy * (1.0f - fx);
            off[k + 3] = rh + xh;  wgt[k + 3] = w * fy * fx;
        }
    }

    // ---- gather+accumulate for CPT channels: pure LDG + FFMA ----
    const int HW = H * W;
    const float* fc = feat + ((size_t)b * C + c0) * (size_t)HW;

    #pragma unroll
    for (int j = 0; j < CPT; j++) {
        const float* f = fc + (size_t)j * cg * HW;   // channel c0 + j*cg
        float acc = 0.0f;
        #pragma unroll
        for (int k = 0; k < 16; k++)
            acc += wgt[k] * __ldg(f + off[k]);
        out[((size_t)n * C + c0 + j * cg) * (POOLED * POOLED) + p] = acc;
    }
}

extern "C" void kernel_launch(void* const* d_in, const int* in_sizes, int n_in,
                              void* d_out, int out_size)
{
    const float* feat = (const float*)d_in[0];   // (2,256,200,200) fp32
    const float* rois = (const float*)d_in[1];   // (512,5) fp32
    float* out = (float*)d_out;                  // (512,256,7,7) fp32

    const int C = 256, H = 200, W = 200;
    int N = in_sizes[1] / 5;
    (void)n_in; (void)out_size;

    int total = N * (C / CPT) * POOLED * POOLED;
    int threads = 256;
    int blocks = (total + threads - 1) / threads;
    roi_align_kernel<<<blocks, threads>>>(feat, rois, out, N, C, H, W);
}